// round 11
// baseline (speedup 1.0000x reference)
#include <cuda_runtime.h>

// Problem constants
#define W_DIM 512
#define H_DIM 512
#define B_DIM 8
#define C_DIM 32
#define NBLK  128           // 8 batches * 16 row-tiles of 32 rows
#define NTHR  256
#define WCH   16            // w-columns staged per chunk

// Halo exchange buffer, (W,B,H,C) layout — ONLY tile-edge rows are written.
__device__ float    g_Yt[W_DIM * B_DIM * H_DIM * C_DIM];   // 256 MB
__device__ unsigned g_progress[NBLK];                       // monotonic counters

// ---- fast math -------------------------------------------------------------
__device__ __forceinline__ float tanh_fast(float x) {
    float y; asm("tanh.approx.f32 %0, %1;" : "=f"(y) : "f"(x)); return y;
}
__device__ __forceinline__ float sigmoid_fast(float x) {
    return fmaf(0.5f, tanh_fast(0.5f * x), 0.5f);
}

// Leader publish: release-exchange at GPU scope (proven R9/R10). All block
// stores happen-before via the preceding __syncthreads (cumulative release).
__device__ __forceinline__ void atom_rel_exch(unsigned* p, unsigned v) {
    unsigned old;
    asm volatile("atom.release.gpu.global.exch.b32 %0, [%1], %2;"
                 : "=r"(old) : "l"(p), "r"(v) : "memory");
}

// ---------------------------------------------------------------------------
// smem layout (floats) — all offsets compile-time constants
//   sWih  : 96 x 100 (stride % 32 == 4 -> conflict-free float4) = 9600
//   sWhh  : 96 x 36                                             = 3456
//   bufA  : 34 x 32  (column + 2 halo slots)                    = 1088
//   bufB  : 34 x 32                                             = 1088
//   sCur  : 32 x 32  (input column; warp-local)                 = 1024
//   sXstg : 16 x 32 x 32  input staging  (wi, r, c)             = 16384
//   sOstg : 16 x 32 x 32  output staging (wi, r, c)             = 16384
// total 49024 floats = 196096 bytes (dynamic)
// ---------------------------------------------------------------------------
#define SM_WIH  0
#define SM_WHH  (SM_WIH + 96 * 100)
#define SM_BUFA (SM_WHH + 96 * 36)
#define SM_BUFB (SM_BUFA + 34 * 32)
#define SM_CUR  (SM_BUFB + 34 * 32)
#define SM_XSTG (SM_CUR + 32 * 32)
#define SM_OSTG (SM_XSTG + WCH * 1024)
#define SM_FLOATS (SM_OSTG + WCH * 1024)

// ---------------------------------------------------------------------------
// Refill input staging with columns w0..w0+15 from states (B,C,H,W).
// Warp-quarter mapping: 4 lanes x float4 = 64B contiguous per (r,c) row
// -> sector-coalesced LDG. STS is 4-way conflicted (acceptable, 1/16 steps).
// ---------------------------------------------------------------------------
__device__ __forceinline__ void refill_x(
    float* __restrict__ sm, const float* __restrict__ states,
    int b, int h0, int tid, int w0)
{
#pragma unroll
    for (int it = 0; it < 16; ++it) {
        const int idx = it * 256 + tid;
        const int rc = idx >> 2, k = idx & 3;
        const int r = rc >> 5, c = rc & 31;
        const float4 v = *(const float4*)
            &states[((size_t)(b * 32 + c) * 512 + (h0 + r)) * 512 + w0 + k * 4];
        sm[SM_XSTG + (k * 4 + 0) * 1024 + rc] = v.x;
        sm[SM_XSTG + (k * 4 + 1) * 1024 + rc] = v.y;
        sm[SM_XSTG + (k * 4 + 2) * 1024 + rc] = v.z;
        sm[SM_XSTG + (k * 4 + 3) * 1024 + rc] = v.w;
    }
}

// Flush output staging (columns w0..w0+15) to out (B,C,H,W).
__device__ __forceinline__ void flush_o(
    float* __restrict__ sm, float* __restrict__ out,
    int b, int h0, int tid, int w0)
{
#pragma unroll
    for (int it = 0; it < 16; ++it) {
        const int idx = it * 256 + tid;
        const int rc = idx >> 2, k = idx & 3;
        const int r = rc >> 5, c = rc & 31;
        float4 v;
        v.x = sm[SM_OSTG + (k * 4 + 0) * 1024 + rc];
        v.y = sm[SM_OSTG + (k * 4 + 1) * 1024 + rc];
        v.z = sm[SM_OSTG + (k * 4 + 2) * 1024 + rc];
        v.w = sm[SM_OSTG + (k * 4 + 3) * 1024 + rc];
        *(float4*)&out[((size_t)(b * 32 + c) * 512 + (h0 + r)) * 512 + w0 + k * 4] = v;
    }
}

// ---------------------------------------------------------------------------
// One scan step (R8/R10-proven structure). PREV/NEXT compile-time offsets.
// Input col from sXstg, output col to sOstg; only edge rows hit g_Yt.
// ---------------------------------------------------------------------------
template<int PREV, int NEXT>
__device__ __forceinline__ void gru_step(
    float* __restrict__ sm, int w,
    int tid, int b, int tile, int h0, int c, int rq, int beta, unsigned sBase,
    float br0, float bz0, float bni, float bnh)
{
    const int wi = (w & (WCH - 1)) * 1024;

    // Current input column: staging -> sCur (warp-local rows), keep in regs
    float cv[4];
#pragma unroll
    for (int i = 0; i < 4; ++i) {
        float v = sm[SM_XSTG + wi + (rq * 4 + i) * 32 + c];
        cv[i] = v;
        sm[SM_CUR + (rq * 4 + i) * 32 + c] = v;
    }

    // Edge warps fetch their own halo row of column w-1 (proven protocol)
    if (rq == 0) {
        if (tile > 0) {
            if ((tid & 31) == 0) {
                const unsigned tgt = sBase + (unsigned)w;
                while (atomicAdd(&g_progress[beta - 1], 0u) < tgt) { }
            }
            __syncwarp();
            float v = __ldcg(&g_Yt[((size_t)((w - 1) * 8 + b) * 512 + (h0 - 1)) * 32 + (tid & 31)]);
            sm[PREV + (tid & 31)] = v;                     // slot 0
        }
    } else if (rq == 7) {
        if (tile < 15) {
            if ((tid & 31) == 0) {
                const unsigned tgt = sBase + (unsigned)w;
                while (atomicAdd(&g_progress[beta + 1], 0u) < tgt) { }
            }
            __syncwarp();
            float v = __ldcg(&g_Yt[((size_t)((w - 1) * 8 + b) * 512 + (h0 + 32)) * 32 + (tid & 31)]);
            sm[PREV + 33 * 32 + (tid & 31)] = v;           // slot 33
        }
    }
    __syncwarp();   // cross-lane visibility of sCur rows + own halo slot

    // ---- compute: 4 rows x 1 channel per thread ---------------------------
    float ar[4], az[4], ani[4], anh[4];
#pragma unroll
    for (int i = 0; i < 4; ++i) { ar[i] = br0; az[i] = bz0; ani[i] = bni; anh[i] = bnh; }

    // i-part: x(96 = prev rows h-1,h,h+1 contiguous in buf slots) @ Wih^T
#pragma unroll 8
    for (int kq = 0; kq < 24; ++kq) {
        float4 wr = *(const float4*)&sm[SM_WIH + (c)      * 100 + kq * 4];
        float4 wz = *(const float4*)&sm[SM_WIH + (32 + c) * 100 + kq * 4];
        float4 wn = *(const float4*)&sm[SM_WIH + (64 + c) * 100 + kq * 4];
#pragma unroll
        for (int i = 0; i < 4; ++i) {
            float4 xv = *(const float4*)&sm[PREV + (rq * 4 + i) * 32 + kq * 4];
            ar[i]  = fmaf(xv.x, wr.x, fmaf(xv.y, wr.y, fmaf(xv.z, wr.z, fmaf(xv.w, wr.w, ar[i]))));
            az[i]  = fmaf(xv.x, wz.x, fmaf(xv.y, wz.y, fmaf(xv.z, wz.z, fmaf(xv.w, wz.w, az[i]))));
            ani[i] = fmaf(xv.x, wn.x, fmaf(xv.y, wn.y, fmaf(xv.z, wn.z, fmaf(xv.w, wn.w, ani[i]))));
        }
    }
    // h-part: cur col (32) @ Whh^T
#pragma unroll
    for (int kq = 0; kq < 8; ++kq) {
        float4 wr = *(const float4*)&sm[SM_WHH + (c)      * 36 + kq * 4];
        float4 wz = *(const float4*)&sm[SM_WHH + (32 + c) * 36 + kq * 4];
        float4 wn = *(const float4*)&sm[SM_WHH + (64 + c) * 36 + kq * 4];
#pragma unroll
        for (int i = 0; i < 4; ++i) {
            float4 hv = *(const float4*)&sm[SM_CUR + (rq * 4 + i) * 32 + kq * 4];
            ar[i]  = fmaf(hv.x, wr.x, fmaf(hv.y, wr.y, fmaf(hv.z, wr.z, fmaf(hv.w, wr.w, ar[i]))));
            az[i]  = fmaf(hv.x, wz.x, fmaf(hv.y, wz.y, fmaf(hv.z, wz.z, fmaf(hv.w, wz.w, az[i]))));
            anh[i] = fmaf(hv.x, wn.x, fmaf(hv.y, wn.y, fmaf(hv.z, wn.z, fmaf(hv.w, wn.w, anh[i]))));
        }
    }

    float outv[4];
#pragma unroll
    for (int i = 0; i < 4; ++i) {
        float rg = sigmoid_fast(ar[i]);
        float zg = sigmoid_fast(az[i]);
        float ng = tanh_fast(fmaf(rg, anh[i], ani[i]));
        outv[i]  = fmaf(ng - cv[i], zg, cv[i]);   // n*z + cur*(1-z)
    }

    // own rows -> NEXT buffer + output staging; edges -> g_Yt for halos
#pragma unroll
    for (int i = 0; i < 4; ++i) {
        int r = rq * 4 + i;
        sm[NEXT + (1 + r) * 32 + c] = outv[i];
        sm[SM_OSTG + wi + r * 32 + c] = outv[i];
    }
    if (rq == 0)
        __stcg(&g_Yt[((size_t)(w * 8 + b) * 512 + h0) * 32 + c], outv[0]);
    else if (rq == 7)
        __stcg(&g_Yt[((size_t)(w * 8 + b) * 512 + (h0 + 31)) * 32 + c], outv[3]);

    __syncthreads();   // the ONLY per-step block barrier
    if (tid == 0) atom_rel_exch(&g_progress[beta], sBase + (unsigned)(w + 1));
}

__global__ __launch_bounds__(NTHR, 1) void scan_kernel(
    const float* __restrict__ states, float* __restrict__ out,
    const float* __restrict__ Wih, const float* __restrict__ bih,
    const float* __restrict__ Whh, const float* __restrict__ bhh)
{
    extern __shared__ float sm[];
    __shared__ unsigned sBaseSh;

    const int tid  = threadIdx.x;
    const int beta = blockIdx.x;
    const int b    = beta >> 4;
    const int tile = beta & 15;
    const int h0   = tile * 32;
    const int c    = tid & 31;        // channel
    const int rq   = tid >> 5;        // warp id = row quad: rows rq*4 .. rq*4+3

    if (tid == 0) sBaseSh = atomicAdd(&g_progress[beta], 0u);

    for (int i = tid; i < 96 * 96; i += NTHR) sm[SM_WIH + (i / 96) * 100 + (i % 96)] = Wih[i];
    for (int i = tid; i < 96 * 32; i += NTHR) sm[SM_WHH + (i / 32) * 36  + (i % 32)] = Whh[i];

    const float br0 = bih[c]      + bhh[c];
    const float bz0 = bih[32 + c] + bhh[32 + c];
    const float bni = bih[64 + c];
    const float bnh = bhh[64 + c];

    // zero halo slots of both buffers (edge tiles never overwrite them)
    if (tid < 32) { sm[SM_BUFA + tid] = 0.0f; sm[SM_BUFB + tid] = 0.0f; }
    else if (tid < 64) {
        sm[SM_BUFA + 33 * 32 + (tid - 32)] = 0.0f;
        sm[SM_BUFB + 33 * 32 + (tid - 32)] = 0.0f;
    }

    // Stage input chunk 0 (w = 0..15)
    refill_x(sm, states, b, h0, tid, 0);
    __syncthreads();
    const unsigned sBase = sBaseSh;

    // Column 0 = input column 0 (identity passthrough)
#pragma unroll
    for (int i = 0; i < 4; ++i) {
        int r = rq * 4 + i;
        float v = sm[SM_XSTG + r * 32 + c];        // wi = 0
        sm[SM_BUFA + (1 + r) * 32 + c] = v;
        sm[SM_OSTG + r * 32 + c] = v;
        if (rq == 0 && i == 0)
            __stcg(&g_Yt[((size_t)b * 512 + h0) * 32 + c], v);
        if (rq == 7 && i == 3)
            __stcg(&g_Yt[((size_t)b * 512 + (h0 + 31)) * 32 + c], v);
    }
    __syncthreads();
    if (tid == 0) atom_rel_exch(&g_progress[beta], sBase + 1);

    // w=1 reads bufA -> writes bufB; then pairs (B->A, A->B).
    gru_step<SM_BUFA, SM_BUFB>(sm, 1, tid, b, tile, h0, c, rq, beta, sBase,
                               br0, bz0, bni, bnh);
    for (int w = 2; w < W_DIM; w += 2) {
        gru_step<SM_BUFB, SM_BUFA>(sm, w,     tid, b, tile, h0, c, rq, beta, sBase,
                                   br0, bz0, bni, bnh);
        gru_step<SM_BUFA, SM_BUFB>(sm, w + 1, tid, b, tile, h0, c, rq, beta, sBase,
                                   br0, bz0, bni, bnh);
        // Chunk boundary: w+1 = 15, 31, ..., 511 (always odd)
        if (((w + 1) & (WCH - 1)) == WCH - 1) {
            flush_o(sm, out, b, h0, tid, (w + 1) - (WCH - 1));
            if (w + 2 < W_DIM)
                refill_x(sm, states, b, h0, tid, w + 2);
            __syncthreads();
        }
    }
}

// ---------------------------------------------------------------------------
extern "C" void kernel_launch(void* const* d_in, const int* in_sizes, int n_in,
                              void* d_out, int out_size) {
    const float* states = (const float*)d_in[0];
    const float* wih    = (const float*)d_in[1];
    const float* bih    = (const float*)d_in[2];
    const float* whh    = (const float*)d_in[3];
    const float* bhh    = (const float*)d_in[4];
    float* out = (float*)d_out;

    cudaFuncSetAttribute(scan_kernel, cudaFuncAttributeMaxDynamicSharedMemorySize,
                         SM_FLOATS * (int)sizeof(float));

    scan_kernel<<<NBLK, NTHR, SM_FLOATS * sizeof(float)>>>(states, out, wih, bih, whh, bhh);
}

// round 12
// speedup vs baseline: 1.5295x; 1.5295x over previous
#include <cuda_runtime.h>

// Problem constants
#define W_DIM 512
#define H_DIM 512
#define B_DIM 8
#define C_DIM 32
#define NBLK  128           // 8 batches * 16 row-tiles of 32 rows
#define NTHR  256

// Scratch: transposed input/output in (W, B, H, C) layout, C contiguous.
__device__ float    g_Xt[W_DIM * B_DIM * H_DIM * C_DIM];   // 256 MB
__device__ float    g_Yt[W_DIM * B_DIM * H_DIM * C_DIM];   // 256 MB
__device__ unsigned g_progress[NBLK];                       // monotonic counters

// ---- fast math -------------------------------------------------------------
__device__ __forceinline__ float tanh_fast(float x) {
    float y; asm("tanh.approx.f32 %0, %1;" : "=f"(y) : "f"(x)); return y;
}
__device__ __forceinline__ float sigmoid_fast(float x) {
    return fmaf(0.5f, tanh_fast(0.5f * x), 0.5f);
}

// Leader publish: release-exchange at GPU scope (proven R10). All block stores
// happen-before via the preceding __syncthreads (cumulative release).
__device__ __forceinline__ void atom_rel_exch(unsigned* p, unsigned v) {
    unsigned old;
    asm volatile("atom.release.gpu.global.exch.b32 %0, [%1], %2;"
                 : "=r"(old) : "l"(p), "r"(v) : "memory");
}

// ---------------------------------------------------------------------------
// Transpose (B,C,H,W) -> (W,B,H,C), 128-wide w-blocks, float4 both sides.
// grid (4, 512, 8), 256 threads. tile[32][132]: rows 16B-aligned (132*4B),
// stride%32==4 -> bounded 4-phase conflicts (= crossbar rate for 128B ops).
// ---------------------------------------------------------------------------
__global__ __launch_bounds__(256) void transpose_in_kernel(const float* __restrict__ states) {
    __shared__ float tile[32][132];
    const int w0 = blockIdx.x * 128, h = blockIdx.y, b = blockIdx.z;
    const int t  = threadIdx.x;

    // Phase 1: read states rows (c fixed per thread-group, w contiguous)
    {
        const int c  = t >> 3;         // 0..31
        const int w8 = t & 7;          // 0..7
        const size_t base = ((size_t)(b * 32 + c) * 512 + h) * 512 + w0;
#pragma unroll
        for (int k = 0; k < 4; ++k) {
            const int wl = w8 * 4 + k * 32;
            float4 v = *(const float4*)&states[base + wl];
            *(float4*)&tile[c][wl] = v;
        }
    }
    __syncthreads();

    // Phase 2: write g_Xt columns (w fixed per thread, c contiguous)
    {
        const int wl    = t >> 1;      // 0..127
        const int chalf = t & 1;       // 0..1
        const size_t base = ((size_t)((w0 + wl) * 8 + b) * 512 + h) * 32 + chalf * 16;
#pragma unroll
        for (int k = 0; k < 4; ++k) {
            float4 v;
            v.x = tile[chalf * 16 + k * 4 + 0][wl];
            v.y = tile[chalf * 16 + k * 4 + 1][wl];
            v.z = tile[chalf * 16 + k * 4 + 2][wl];
            v.w = tile[chalf * 16 + k * 4 + 3][wl];
            *(float4*)&g_Xt[base + k * 4] = v;
        }
    }
}

// ---------------------------------------------------------------------------
// Transpose (W,B,H,C) -> (B,C,H,W), mirror of the above.
// ---------------------------------------------------------------------------
__global__ __launch_bounds__(256) void transpose_out_kernel(float* __restrict__ out) {
    __shared__ float tile[32][132];
    const int w0 = blockIdx.x * 128, h = blockIdx.y, b = blockIdx.z;
    const int t  = threadIdx.x;

    // Phase 1: read g_Yt columns (w fixed per thread, c contiguous)
    {
        const int wl    = t >> 1;      // 0..127
        const int chalf = t & 1;       // 0..1
        const size_t base = ((size_t)((w0 + wl) * 8 + b) * 512 + h) * 32 + chalf * 16;
#pragma unroll
        for (int k = 0; k < 4; ++k) {
            float4 v = *(const float4*)&g_Yt[base + k * 4];
            tile[chalf * 16 + k * 4 + 0][wl] = v.x;
            tile[chalf * 16 + k * 4 + 1][wl] = v.y;
            tile[chalf * 16 + k * 4 + 2][wl] = v.z;
            tile[chalf * 16 + k * 4 + 3][wl] = v.w;
        }
    }
    __syncthreads();

    // Phase 2: write out rows (c fixed per thread-group, w contiguous)
    {
        const int c  = t >> 3;         // 0..31
        const int w8 = t & 7;          // 0..7
        const size_t base = ((size_t)(b * 32 + c) * 512 + h) * 512 + w0;
#pragma unroll
        for (int k = 0; k < 4; ++k) {
            const int wl = w8 * 4 + k * 32;
            float4 v = *(const float4*)&tile[c][wl];
            *(float4*)&out[base + wl] = v;
        }
    }
}

// ---------------------------------------------------------------------------
// smem layout (floats) — all offsets compile-time constants
//   sWih : 96 x 100 (stride % 32 == 4 -> conflict-free float4) = 9600
//   sWhh : 96 x 36                                             = 3456
//   bufA : 34 x 32  (column + 2 halo slots)                    = 1088
//   bufB : 34 x 32                                             = 1088
//   sCur : 32 x 32  (input column; warp-local, single buffer)  = 1024
// total 16256 floats = 65024 bytes (dynamic)
// ---------------------------------------------------------------------------
#define SM_WIH  0
#define SM_WHH  (SM_WIH + 96 * 100)
#define SM_BUFA (SM_WHH + 96 * 36)
#define SM_BUFB (SM_BUFA + 34 * 32)
#define SM_CUR  (SM_BUFB + 34 * 32)
#define SM_FLOATS (SM_CUR + 32 * 32)

// ---------------------------------------------------------------------------
// One scan step (R10-proven, 1996us — byte-identical). PREV/NEXT compile-time
// smem offsets. Sync per step: __syncwarp (warp-local sCur/halo) + ONE
// __syncthreads, then leader release-exchange publishes the flag.
// ---------------------------------------------------------------------------
template<int PREV, int NEXT>
__device__ __forceinline__ void gru_step(
    float* __restrict__ sm, int w, float4& xnext,
    int tid, int b, int tile, int h0, int c, int rq, int beta, unsigned sBase,
    float br0, float bz0, float bni, float bnh)
{
    // Own-row input-column store from prefetch register; issue next prefetch
    ((float4*)(sm + SM_CUR))[tid] = xnext;
    if (w + 1 < W_DIM)
        xnext = *(const float4*)&g_Xt[((size_t)((w + 1) * 8 + b) * 512 + h0) * 32 + tid * 4];

    // Edge warps fetch their own halo row of column w-1
    if (rq == 0) {
        if (tile > 0) {
            if ((tid & 31) == 0) {
                const unsigned tgt = sBase + (unsigned)w;
                while (atomicAdd(&g_progress[beta - 1], 0u) < tgt) { }
            }
            __syncwarp();
            float v = __ldcg(&g_Yt[((size_t)((w - 1) * 8 + b) * 512 + (h0 - 1)) * 32 + (tid & 31)]);
            sm[PREV + (tid & 31)] = v;                     // slot 0
        }
    } else if (rq == 7) {
        if (tile < 15) {
            if ((tid & 31) == 0) {
                const unsigned tgt = sBase + (unsigned)w;
                while (atomicAdd(&g_progress[beta + 1], 0u) < tgt) { }
            }
            __syncwarp();
            float v = __ldcg(&g_Yt[((size_t)((w - 1) * 8 + b) * 512 + (h0 + 32)) * 32 + (tid & 31)]);
            sm[PREV + 33 * 32 + (tid & 31)] = v;           // slot 33
        }
    }
    __syncwarp();   // cross-lane visibility of sCur rows + own halo slot

    // ---- compute: 4 rows x 1 channel per thread ---------------------------
    float ar[4], az[4], ani[4], anh[4];
#pragma unroll
    for (int i = 0; i < 4; ++i) { ar[i] = br0; az[i] = bz0; ani[i] = bni; anh[i] = bnh; }

    // i-part: x(96 = prev rows h-1,h,h+1 contiguous in buf slots) @ Wih^T
#pragma unroll 8
    for (int kq = 0; kq < 24; ++kq) {
        float4 wr = *(const float4*)&sm[SM_WIH + (c)      * 100 + kq * 4];
        float4 wz = *(const float4*)&sm[SM_WIH + (32 + c) * 100 + kq * 4];
        float4 wn = *(const float4*)&sm[SM_WIH + (64 + c) * 100 + kq * 4];
#pragma unroll
        for (int i = 0; i < 4; ++i) {
            float4 xv = *(const float4*)&sm[PREV + (rq * 4 + i) * 32 + kq * 4];
            ar[i]  = fmaf(xv.x, wr.x, fmaf(xv.y, wr.y, fmaf(xv.z, wr.z, fmaf(xv.w, wr.w, ar[i]))));
            az[i]  = fmaf(xv.x, wz.x, fmaf(xv.y, wz.y, fmaf(xv.z, wz.z, fmaf(xv.w, wz.w, az[i]))));
            ani[i] = fmaf(xv.x, wn.x, fmaf(xv.y, wn.y, fmaf(xv.z, wn.z, fmaf(xv.w, wn.w, ani[i]))));
        }
    }
    // h-part: cur col (32) @ Whh^T
#pragma unroll
    for (int kq = 0; kq < 8; ++kq) {
        float4 wr = *(const float4*)&sm[SM_WHH + (c)      * 36 + kq * 4];
        float4 wz = *(const float4*)&sm[SM_WHH + (32 + c) * 36 + kq * 4];
        float4 wn = *(const float4*)&sm[SM_WHH + (64 + c) * 36 + kq * 4];
#pragma unroll
        for (int i = 0; i < 4; ++i) {
            float4 hv = *(const float4*)&sm[SM_CUR + (rq * 4 + i) * 32 + kq * 4];
            ar[i]  = fmaf(hv.x, wr.x, fmaf(hv.y, wr.y, fmaf(hv.z, wr.z, fmaf(hv.w, wr.w, ar[i]))));
            az[i]  = fmaf(hv.x, wz.x, fmaf(hv.y, wz.y, fmaf(hv.z, wz.z, fmaf(hv.w, wz.w, az[i]))));
            anh[i] = fmaf(hv.x, wn.x, fmaf(hv.y, wn.y, fmaf(hv.z, wn.z, fmaf(hv.w, wn.w, anh[i]))));
        }
    }

    float outv[4];
#pragma unroll
    for (int i = 0; i < 4; ++i) {
        float rg = sigmoid_fast(ar[i]);
        float zg = sigmoid_fast(az[i]);
        float ng = tanh_fast(fmaf(rg, anh[i], ani[i]));
        float cv = sm[SM_CUR + (rq * 4 + i) * 32 + c];
        outv[i]  = fmaf(ng - cv, zg, cv);   // n*z + cur*(1-z)
    }

    // write own rows into the NEXT buffer (WAR-free) + global output
#pragma unroll
    for (int i = 0; i < 4; ++i) {
        int r = rq * 4 + i;
        sm[NEXT + (1 + r) * 32 + c] = outv[i];
        g_Yt[((size_t)(w * 8 + b) * 512 + (h0 + r)) * 32 + c] = outv[i];
    }
    __syncthreads();   // the ONLY block barrier: tile handoff + happens-before
    if (tid == 0) atom_rel_exch(&g_progress[beta], sBase + (unsigned)(w + 1));
}

__global__ __launch_bounds__(NTHR, 1) void scan_kernel(
    const float* __restrict__ Wih, const float* __restrict__ bih,
    const float* __restrict__ Whh, const float* __restrict__ bhh)
{
    extern __shared__ float sm[];
    __shared__ unsigned sBaseSh;

    const int tid  = threadIdx.x;
    const int beta = blockIdx.x;
    const int b    = beta >> 4;
    const int tile = beta & 15;
    const int h0   = tile * 32;
    const int c    = tid & 31;        // channel
    const int rq   = tid >> 5;        // warp id = row quad: rows rq*4 .. rq*4+3

    if (tid == 0) sBaseSh = atomicAdd(&g_progress[beta], 0u);

    for (int i = tid; i < 96 * 96; i += NTHR) sm[SM_WIH + (i / 96) * 100 + (i % 96)] = Wih[i];
    for (int i = tid; i < 96 * 32; i += NTHR) sm[SM_WHH + (i / 32) * 36  + (i % 32)] = Whh[i];

    const float br0 = bih[c]      + bhh[c];
    const float bz0 = bih[32 + c] + bhh[32 + c];
    const float bni = bih[64 + c];
    const float bnh = bhh[64 + c];

    // zero halo slots of both buffers (edge tiles never overwrite them)
    if (tid < 32) { sm[SM_BUFA + tid] = 0.0f; sm[SM_BUFB + tid] = 0.0f; }
    else if (tid < 64) {
        sm[SM_BUFA + 33 * 32 + (tid - 32)] = 0.0f;
        sm[SM_BUFB + 33 * 32 + (tid - 32)] = 0.0f;
    }
    __syncthreads();
    const unsigned sBase = sBaseSh;

    // Publish column 0 = input column 0 (identity passthrough) into bufA
    for (int i = tid; i < 1024; i += NTHR) {
        int r = i >> 5, cc = i & 31;
        size_t gi = ((size_t)b * 512 + (h0 + r)) * 32 + cc;   // w = 0
        float v = g_Xt[gi];
        sm[SM_BUFA + (1 + r) * 32 + cc] = v;
        g_Yt[gi] = v;
    }
    __syncthreads();
    if (tid == 0) atom_rel_exch(&g_progress[beta], sBase + 1);

    // Prefetch input column w=1 into registers (off the critical path)
    float4 xnext = *(const float4*)&g_Xt[((size_t)(1 * 8 + b) * 512 + h0) * 32 + tid * 4];

    // w=1 reads bufA -> writes bufB; then pairs (B->A, A->B)
    gru_step<SM_BUFA, SM_BUFB>(sm, 1, xnext, tid, b, tile, h0, c, rq, beta, sBase,
                               br0, bz0, bni, bnh);
    for (int w = 2; w < W_DIM; w += 2) {
        gru_step<SM_BUFB, SM_BUFA>(sm, w,     xnext, tid, b, tile, h0, c, rq, beta, sBase,
                                   br0, bz0, bni, bnh);
        gru_step<SM_BUFA, SM_BUFB>(sm, w + 1, xnext, tid, b, tile, h0, c, rq, beta, sBase,
                                   br0, bz0, bni, bnh);
    }
}

// ---------------------------------------------------------------------------
extern "C" void kernel_launch(void* const* d_in, const int* in_sizes, int n_in,
                              void* d_out, int out_size) {
    const float* states = (const float*)d_in[0];
    const float* wih    = (const float*)d_in[1];
    const float* bih    = (const float*)d_in[2];
    const float* whh    = (const float*)d_in[3];
    const float* bhh    = (const float*)d_in[4];
    float* out = (float*)d_out;

    cudaFuncSetAttribute(scan_kernel, cudaFuncAttributeMaxDynamicSharedMemorySize,
                         SM_FLOATS * (int)sizeof(float));

    dim3 tgrid(W_DIM / 128, H_DIM, B_DIM);
    transpose_in_kernel<<<tgrid, 256>>>(states);
    scan_kernel<<<NBLK, NTHR, SM_FLOATS * sizeof(float)>>>(wih, bih, whh, bhh);
    transpose_out_kernel<<<tgrid, 256>>>(out);
}